// round 2
// baseline (speedup 1.0000x reference)
#include <cuda_runtime.h>
#include <cstdint>
#include <math.h>

#define BB 16384
#define CC 512
#define DD 512
#define HH 1024

// ---------------------------------------------------------------------------
// JAX threefry2x32 (exact), PARTITIONABLE mode (jax_threefry_partitionable=True,
// the default in modern JAX):
//   split(key, n)[i]          = threefry2x32(key, (hi32(i), lo32(i)))  (both lanes)
//   random_bits(key,32,..)[j] = out0 ^ out1 of threefry2x32(key, (0, j))
// ---------------------------------------------------------------------------
struct U2 { unsigned a, b; };

__host__ __device__ constexpr unsigned rotl32(unsigned v, int r) {
    return (v << r) | (v >> (32 - r));
}

__host__ __device__ constexpr U2 tf2x32(unsigned k0, unsigned k1, unsigned x0, unsigned x1) {
    unsigned ks2 = 0x1BD11BDAu ^ k0 ^ k1;
    x0 += k0; x1 += k1;
#define TFR(r) { x0 += x1; x1 = rotl32(x1, (r)); x1 ^= x0; }
    TFR(13) TFR(15) TFR(26) TFR(6)
    x0 += k1;  x1 += ks2 + 1u;
    TFR(17) TFR(29) TFR(16) TFR(24)
    x0 += ks2; x1 += k0 + 2u;
    TFR(13) TFR(15) TFR(26) TFR(6)
    x0 += k0;  x1 += k1 + 3u;
    TFR(17) TFR(29) TFR(16) TFR(24)
    x0 += k1;  x1 += ks2 + 4u;
    TFR(13) TFR(15) TFR(26) TFR(6)
    x0 += ks2; x1 += k0 + 5u;
#undef TFR
    return U2{x0, x1};
}

// Root: jax.random.key(42) -> (0, 42); split -> fold-in of counter i
constexpr U2 ROOT_K1 = tf2x32(0u, 42u, 0u, 0u);  // -> e_sp gate
constexpr U2 ROOT_K2 = tf2x32(0u, 42u, 0u, 1u);  // -> e_dyn gate

// Per-step injection constants, fully precomputed at compile time.
// Layout per step: [x0_init, x1_init, (x0_inj, x1_inj) x 5 groups]
struct Step12 { unsigned c[12]; };
struct Tab { Step12 s[32]; };

constexpr Tab make_tab(unsigned K0, unsigned K1) {
    Tab t{};
    for (int i = 0; i < 32; ++i) {
        U2 kp = tf2x32(K0, K1, 0u, (unsigned)i);   // split(key, 32)[i]
        unsigned k0 = kp.a, k1 = kp.b;
        unsigned ks2 = 0x1BD11BDAu ^ k0 ^ k1;
        unsigned* c = t.s[i].c;
        c[0]  = k0;   c[1]  = k1;        // initial injection (x0 starts at 0, x1 at j)
        c[2]  = k1;   c[3]  = ks2 + 1u;
        c[4]  = ks2;  c[5]  = k0 + 2u;
        c[6]  = k0;   c[7]  = k1 + 3u;
        c[8]  = k1;   c[9]  = ks2 + 4u;
        c[10] = ks2;  c[11] = k0 + 5u;
    }
    return t;
}

__constant__ Tab TAB_SP  = make_tab(ROOT_K1.a, ROOT_K1.b);
__constant__ Tab TAB_DYN = make_tab(ROOT_K2.a, ROOT_K2.b);

// threefry2x32 with precomputed injections; returns out0 ^ out1 (32-bit
// partitionable random_bits). counts = (0, j).
__device__ __forceinline__ unsigned tf_bits(const unsigned* __restrict__ c, unsigned j) {
    unsigned x0 = c[0];
    unsigned x1 = j + c[1];
#define TFR(r) { x0 += x1; x1 = rotl32(x1, (r)); x1 ^= x0; }
    TFR(13) TFR(15) TFR(26) TFR(6)
    x0 += c[2];  x1 += c[3];
    TFR(17) TFR(29) TFR(16) TFR(24)
    x0 += c[4];  x1 += c[5];
    TFR(13) TFR(15) TFR(26) TFR(6)
    x0 += c[6];  x1 += c[7];
    TFR(17) TFR(29) TFR(16) TFR(24)
    x0 += c[8];  x1 += c[9];
    TFR(13) TFR(15) TFR(26) TFR(6)
    x0 += c[10]; x1 += c[11];
#undef TFR
    return x0 ^ x1;
}

// ---------------------------------------------------------------------------
// bits -> N(0,1): uniform in (lo, 1), sqrt(2)*erfinv (XLA Giles polynomial)
// ---------------------------------------------------------------------------
__device__ __forceinline__ float normal_from_bits(unsigned bits) {
    float f = __uint_as_float((bits >> 9) | 0x3f800000u) - 1.0f;   // [0, 1)
    float x = fmaf(f, 1.99999994f, -0.99999994f);                  // (lo, 1)
    float w = -__logf(fmaf(x, -x, 1.0f));                          // -log(1-x^2)
    float p;
    if (w < 5.0f) {
        w -= 2.5f;
        p = 2.81022636e-08f;
        p = fmaf(p, w, 3.43273939e-07f);
        p = fmaf(p, w, -3.5233877e-06f);
        p = fmaf(p, w, -4.39150654e-06f);
        p = fmaf(p, w, 0.00021858087f);
        p = fmaf(p, w, -0.00125372503f);
        p = fmaf(p, w, -0.00417768164f);
        p = fmaf(p, w, 0.246640727f);
        p = fmaf(p, w, 1.50140941f);
    } else {
        w = sqrtf(w) - 3.0f;
        p = -0.000200214257f;
        p = fmaf(p, w, 0.000100950558f);
        p = fmaf(p, w, 0.00134934322f);
        p = fmaf(p, w, -0.00367342844f);
        p = fmaf(p, w, 0.00573950773f);
        p = fmaf(p, w, -0.0076224613f);
        p = fmaf(p, w, 0.00943887047f);
        p = fmaf(p, w, 1.00167406f);
        p = fmaf(p, w, 2.83297682f);
    }
    return 1.41421354f * (p * x);   // sqrt(2) * erfinv(x)
}

// ---------------------------------------------------------------------------
// Scratch (device globals: no allocation allowed)
// ---------------------------------------------------------------------------
__device__ float g_h[BB * HH];       // hidden (reused for both MLPs)
__device__ float g_e[BB * CC];       // e_dyn, overwritten in-place with gate
__device__ float g_conc[BB * CC];    // concentration * gate
__device__ float g_comps[CC * DD];   // |vanilla| * p_sp

// ---------------------------------------------------------------------------
// Langevin gate: u_{t+1} = u - 0.05*(u+e) + 0.1*n_t, 32 steps, p = sigmoid(-u)
// 2 consecutive elements per thread (ILP + coalesced float2 I/O).
// Step loop kept rolled (body fits L0 I$); injections via LDCU (uniform pipe).
// ---------------------------------------------------------------------------
template <bool MASK>
__global__ void __launch_bounds__(256)
langevin_kernel(const float* __restrict__ ein, const float* __restrict__ vanilla,
                float* __restrict__ out, int half_pairs, const int tab_sel) {
    int p0 = blockIdx.x * blockDim.x + threadIdx.x;
    if (p0 >= half_pairs) return;
    unsigned j = 2u * (unsigned)p0;
    const Tab* tab = tab_sel ? &TAB_DYN : &TAB_SP;

    float2 ev = *reinterpret_cast<const float2*>(ein + j);
    float e0 = ev.x, e1 = ev.y;
    float u0 = 0.f, u1 = 0.f;
#pragma unroll 1
    for (int t = 0; t < 32; ++t) {
        const unsigned* c = tab->s[t].c;
        unsigned b0 = tf_bits(c, j);
        unsigned b1 = tf_bits(c, j + 1u);
        float n0 = normal_from_bits(b0);
        float n1 = normal_from_bits(b1);
        u0 = u0 - 0.05f * (u0 + e0) + 0.1f * n0;
        u1 = u1 - 0.05f * (u1 + e1) + 0.1f * n1;
    }
    float g0 = 1.f / (1.f + __expf(u0));   // sigmoid(-u/tau), tau=1
    float g1 = 1.f / (1.f + __expf(u1));
    float2 o;
    if (MASK) {
        float2 vv = *reinterpret_cast<const float2*>(vanilla + j);
        o.x = fabsf(vv.x) * g0;
        o.y = fabsf(vv.y) * g1;
    } else {
        o.x = g0; o.y = g1;
    }
    *reinterpret_cast<float2*>(out + j) = o;
}

// ---------------------------------------------------------------------------
// SGEMM: C[M,N] = A[M,K] @ B[K,N] (+bias)(relu|*gate). 128x128x8, 256 thr,
// 8x8 microtile. All dims multiples of 128/8 -> guard-free.
// EPI: 0 = relu(acc+bias), 1 = acc+bias, 2 = (acc+bias)*gate, 3 = acc
// ---------------------------------------------------------------------------
template <int EPI>
__global__ void __launch_bounds__(256)
sgemm_kernel(const float* __restrict__ A, const float* __restrict__ B,
             const float* __restrict__ bias, const float* __restrict__ gate,
             float* __restrict__ C, int M, int N, int K) {
    __shared__ float As[8][128];
    __shared__ float Bs[8][128];

    const int tid = threadIdx.x;
    const int tx = tid & 15;
    const int ty = tid >> 4;
    const int bx = blockIdx.x;
    const int by = blockIdx.y;

    const float* Ab = A + (size_t)by * 128 * K;
    const float* Bb = B + (size_t)bx * 128;

    const int arow = tid >> 1;
    const int acol = (tid & 1) * 4;
    const int brow = tid >> 5;
    const int bcol = (tid & 31) * 4;

    float acc[8][8];
#pragma unroll
    for (int i = 0; i < 8; ++i)
#pragma unroll
        for (int j = 0; j < 8; ++j) acc[i][j] = 0.f;

    for (int k0 = 0; k0 < K; k0 += 8) {
        float4 av = *reinterpret_cast<const float4*>(Ab + (size_t)arow * K + k0 + acol);
        float4 bv = *reinterpret_cast<const float4*>(Bb + (size_t)(k0 + brow) * N + bcol);
        __syncthreads();
        As[acol + 0][arow] = av.x;
        As[acol + 1][arow] = av.y;
        As[acol + 2][arow] = av.z;
        As[acol + 3][arow] = av.w;
        *reinterpret_cast<float4*>(&Bs[brow][bcol]) = bv;
        __syncthreads();
#pragma unroll
        for (int kk = 0; kk < 8; ++kk) {
            float4 a0 = *reinterpret_cast<const float4*>(&As[kk][ty * 8]);
            float4 a1 = *reinterpret_cast<const float4*>(&As[kk][ty * 8 + 4]);
            float4 b0 = *reinterpret_cast<const float4*>(&Bs[kk][tx * 8]);
            float4 b1 = *reinterpret_cast<const float4*>(&Bs[kk][tx * 8 + 4]);
            float ar[8] = {a0.x, a0.y, a0.z, a0.w, a1.x, a1.y, a1.z, a1.w};
            float br[8] = {b0.x, b0.y, b0.z, b0.w, b1.x, b1.y, b1.z, b1.w};
#pragma unroll
            for (int i = 0; i < 8; ++i)
#pragma unroll
                for (int j = 0; j < 8; ++j)
                    acc[i][j] = fmaf(ar[i], br[j], acc[i][j]);
        }
    }

    const int mbase = by * 128 + ty * 8;
    const int nbase = bx * 128 + tx * 8;
#pragma unroll
    for (int i = 0; i < 8; ++i) {
        size_t row = (size_t)(mbase + i) * N;
#pragma unroll
        for (int j = 0; j < 8; ++j) {
            float v = acc[i][j];
            if (EPI == 0) v = fmaxf(v + bias[nbase + j], 0.f);
            if (EPI == 1) v = v + bias[nbase + j];
            if (EPI == 2) v = (v + bias[nbase + j]) * gate[row + nbase + j];
            C[row + nbase + j] = v;
        }
    }
}

// ---------------------------------------------------------------------------
extern "C" void kernel_launch(void* const* d_in, const int* in_sizes, int n_in,
                              void* d_out, int out_size) {
    const float* x    = (const float*)d_in[0];
    const float* van  = (const float*)d_in[1];
    const float* e_sp = (const float*)d_in[2];
    const float* W1e  = (const float*)d_in[3];
    const float* b1e  = (const float*)d_in[4];
    const float* W2e  = (const float*)d_in[5];
    const float* b2e  = (const float*)d_in[6];
    const float* W1r  = (const float*)d_in[7];
    const float* b1r  = (const float*)d_in[8];
    const float* W2r  = (const float*)d_in[9];
    const float* b2r  = (const float*)d_in[10];
    float* out = (float*)d_out;

    float *ph, *pe, *pconc, *pcomps;
    cudaGetSymbolAddress((void**)&ph, g_h);
    cudaGetSymbolAddress((void**)&pe, g_e);
    cudaGetSymbolAddress((void**)&pconc, g_conc);
    cudaGetSymbolAddress((void**)&pcomps, g_comps);

    // static sparsity mask on components (independent of MLP chain)
    langevin_kernel<true><<<(CC * DD / 2 + 255) / 256, 256>>>(e_sp, van, pcomps,
                                                              CC * DD / 2, 0);

    // energy MLP
    sgemm_kernel<0><<<dim3(HH / 128, BB / 128), 256>>>(x, W1e, b1e, nullptr, ph, BB, HH, DD);
    sgemm_kernel<1><<<dim3(CC / 128, BB / 128), 256>>>(ph, W2e, b2e, nullptr, pe, BB, CC, HH);

    // Langevin gate on e_dyn (in-place)
    langevin_kernel<false><<<(BB * CC / 2 + 255) / 256, 256>>>(pe, nullptr, pe,
                                                               BB * CC / 2, 1);

    // regressor MLP (+ gated epilogue)
    sgemm_kernel<0><<<dim3(HH / 128, BB / 128), 256>>>(x, W1r, b1r, nullptr, ph, BB, HH, DD);
    sgemm_kernel<2><<<dim3(CC / 128, BB / 128), 256>>>(ph, W2r, b2r, pe, pconc, BB, CC, HH);

    // aggregate
    sgemm_kernel<3><<<dim3(DD / 128, BB / 128), 256>>>(pconc, pcomps, nullptr, nullptr, out, BB, DD, CC);
}

// round 4
// speedup vs baseline: 1.3779x; 1.3779x over previous
#include <cuda_runtime.h>
#include <cuda_bf16.h>
#include <cstdint>
#include <math.h>

#define BB 16384
#define CC 512
#define DD 512
#define HH 1024

// ===========================================================================
// JAX threefry2x32 (exact), PARTITIONABLE mode — validated in round 2
// ===========================================================================
struct U2 { unsigned a, b; };

__host__ __device__ constexpr unsigned rotl32(unsigned v, int r) {
    return (v << r) | (v >> (32 - r));
}

__host__ __device__ constexpr U2 tf2x32(unsigned k0, unsigned k1, unsigned x0, unsigned x1) {
    unsigned ks2 = 0x1BD11BDAu ^ k0 ^ k1;
    x0 += k0; x1 += k1;
#define TFR(r) { x0 += x1; x1 = rotl32(x1, (r)); x1 ^= x0; }
    TFR(13) TFR(15) TFR(26) TFR(6)
    x0 += k1;  x1 += ks2 + 1u;
    TFR(17) TFR(29) TFR(16) TFR(24)
    x0 += ks2; x1 += k0 + 2u;
    TFR(13) TFR(15) TFR(26) TFR(6)
    x0 += k0;  x1 += k1 + 3u;
    TFR(17) TFR(29) TFR(16) TFR(24)
    x0 += k1;  x1 += ks2 + 4u;
    TFR(13) TFR(15) TFR(26) TFR(6)
    x0 += ks2; x1 += k0 + 5u;
#undef TFR
    return U2{x0, x1};
}

constexpr U2 ROOT_K1 = tf2x32(0u, 42u, 0u, 0u);
constexpr U2 ROOT_K2 = tf2x32(0u, 42u, 0u, 1u);

struct Step12 { unsigned c[12]; };
struct Tab { Step12 s[32]; };

constexpr Tab make_tab(unsigned K0, unsigned K1) {
    Tab t{};
    for (int i = 0; i < 32; ++i) {
        U2 kp = tf2x32(K0, K1, 0u, (unsigned)i);
        unsigned k0 = kp.a, k1 = kp.b;
        unsigned ks2 = 0x1BD11BDAu ^ k0 ^ k1;
        unsigned* c = t.s[i].c;
        c[0]  = k0;   c[1]  = k1;
        c[2]  = k1;   c[3]  = ks2 + 1u;
        c[4]  = ks2;  c[5]  = k0 + 2u;
        c[6]  = k0;   c[7]  = k1 + 3u;
        c[8]  = k1;   c[9]  = ks2 + 4u;
        c[10] = ks2;  c[11] = k0 + 5u;
    }
    return t;
}

__constant__ Tab TAB_SP  = make_tab(ROOT_K1.a, ROOT_K1.b);
__constant__ Tab TAB_DYN = make_tab(ROOT_K2.a, ROOT_K2.b);

__device__ __forceinline__ unsigned tf_bits(const unsigned* __restrict__ c, unsigned j) {
    unsigned x0 = c[0];
    unsigned x1 = j + c[1];
#define TFR(r) { x0 += x1; x1 = rotl32(x1, (r)); x1 ^= x0; }
    TFR(13) TFR(15) TFR(26) TFR(6)
    x0 += c[2];  x1 += c[3];
    TFR(17) TFR(29) TFR(16) TFR(24)
    x0 += c[4];  x1 += c[5];
    TFR(13) TFR(15) TFR(26) TFR(6)
    x0 += c[6];  x1 += c[7];
    TFR(17) TFR(29) TFR(16) TFR(24)
    x0 += c[8];  x1 += c[9];
    TFR(13) TFR(15) TFR(26) TFR(6)
    x0 += c[10]; x1 += c[11];
#undef TFR
    return x0 ^ x1;
}

__device__ __forceinline__ float normal_from_bits(unsigned bits) {
    float f = __uint_as_float((bits >> 9) | 0x3f800000u) - 1.0f;
    float x = fmaf(f, 1.99999994f, -0.99999994f);
    float w = -__logf(fmaf(x, -x, 1.0f));
    float p;
    if (w < 5.0f) {
        w -= 2.5f;
        p = 2.81022636e-08f;
        p = fmaf(p, w, 3.43273939e-07f);
        p = fmaf(p, w, -3.5233877e-06f);
        p = fmaf(p, w, -4.39150654e-06f);
        p = fmaf(p, w, 0.00021858087f);
        p = fmaf(p, w, -0.00125372503f);
        p = fmaf(p, w, -0.00417768164f);
        p = fmaf(p, w, 0.246640727f);
        p = fmaf(p, w, 1.50140941f);
    } else {
        w = sqrtf(w) - 3.0f;
        p = -0.000200214257f;
        p = fmaf(p, w, 0.000100950558f);
        p = fmaf(p, w, 0.00134934322f);
        p = fmaf(p, w, -0.00367342844f);
        p = fmaf(p, w, 0.00573950773f);
        p = fmaf(p, w, -0.0076224613f);
        p = fmaf(p, w, 0.00943887047f);
        p = fmaf(p, w, 1.00167406f);
        p = fmaf(p, w, 2.83297682f);
    }
    return 1.41421354f * (p * x);
}

// ===========================================================================
// Scratch (device globals)
// ===========================================================================
__device__ __align__(256) __nv_bfloat16 g_x_hi[BB * DD], g_x_lo[BB * DD];
__device__ __align__(256) __nv_bfloat16 g_h_hi[BB * HH], g_h_lo[BB * HH];
__device__ __align__(256) __nv_bfloat16 g_c_hi[BB * CC], g_c_lo[BB * CC];
__device__ __align__(256) __nv_bfloat16 g_ct_hi[DD * CC], g_ct_lo[DD * CC];
__device__ __align__(256) __nv_bfloat16 g_wt_hi[4 * HH * DD], g_wt_lo[4 * HH * DD];
__device__ __align__(256) float g_e[BB * CC];   // e_dyn -> gate (in place)

__device__ __forceinline__ void split_bf16(float v, __nv_bfloat16& h, __nv_bfloat16& l) {
    h = __float2bfloat16_rn(v);
    l = __float2bfloat16_rn(v - __bfloat162float(h));
}

// ===========================================================================
// Langevin gates (bit-exact, validated round 2)
// ===========================================================================
__global__ void mask_comps_kernel(const float* __restrict__ vanilla,
                                  const float* __restrict__ e_sp,
                                  __nv_bfloat16* __restrict__ ct_hi,
                                  __nv_bfloat16* __restrict__ ct_lo) {
    const int half = (CC * DD) / 2;
    int p0 = blockIdx.x * blockDim.x + threadIdx.x;
    if (p0 >= half) return;
    unsigned j = 2u * (unsigned)p0;
    float2 ev = *reinterpret_cast<const float2*>(e_sp + j);
    float u0 = 0.f, u1 = 0.f;
#pragma unroll 1
    for (int t = 0; t < 32; ++t) {
        const unsigned* c = TAB_SP.s[t].c;
        float n0 = normal_from_bits(tf_bits(c, j));
        float n1 = normal_from_bits(tf_bits(c, j + 1u));
        u0 = u0 - 0.05f * (u0 + ev.x) + 0.1f * n0;
        u1 = u1 - 0.05f * (u1 + ev.y) + 0.1f * n1;
    }
    float g0 = 1.f / (1.f + __expf(u0));
    float g1 = 1.f / (1.f + __expf(u1));
    float2 vv = *reinterpret_cast<const float2*>(vanilla + j);
    float v0 = fabsf(vv.x) * g0;
    float v1 = fabsf(vv.y) * g1;
    int c_row = (int)(j >> 9);
    int d_col = (int)(j & 511u);
    __nv_bfloat16 h, l;
    split_bf16(v0, h, l);
    ct_hi[(size_t)d_col * CC + c_row] = h;  ct_lo[(size_t)d_col * CC + c_row] = l;
    split_bf16(v1, h, l);
    ct_hi[(size_t)(d_col + 1) * CC + c_row] = h;  ct_lo[(size_t)(d_col + 1) * CC + c_row] = l;
}

__global__ void gate_kernel(float* __restrict__ e) {
    const int half = (BB * CC) / 2;
    int p0 = blockIdx.x * blockDim.x + threadIdx.x;
    if (p0 >= half) return;
    unsigned j = 2u * (unsigned)p0;
    float2 ev = *reinterpret_cast<const float2*>(e + j);
    float u0 = 0.f, u1 = 0.f;
#pragma unroll 1
    for (int t = 0; t < 32; ++t) {
        const unsigned* c = TAB_DYN.s[t].c;
        float n0 = normal_from_bits(tf_bits(c, j));
        float n1 = normal_from_bits(tf_bits(c, j + 1u));
        u0 = u0 - 0.05f * (u0 + ev.x) + 0.1f * n0;
        u1 = u1 - 0.05f * (u1 + ev.y) + 0.1f * n1;
    }
    float2 o;
    o.x = 1.f / (1.f + __expf(u0));
    o.y = 1.f / (1.f + __expf(u1));
    *reinterpret_cast<float2*>(e + j) = o;
}

// ===========================================================================
// conversions
// ===========================================================================
__global__ void cvt_split_kernel(const float* __restrict__ in,
                                 __nv_bfloat16* __restrict__ hi,
                                 __nv_bfloat16* __restrict__ lo, int n) {
    int i = blockIdx.x * blockDim.x + threadIdx.x;
    if (i >= n) return;
    __nv_bfloat16 h, l;
    split_bf16(in[i], h, l);
    hi[i] = h; lo[i] = l;
}

__global__ void wsplit_kernel(const float* __restrict__ W,
                              __nv_bfloat16* __restrict__ hi,
                              __nv_bfloat16* __restrict__ lo, int K, int N) {
    int i = blockIdx.x * blockDim.x + threadIdx.x;
    if (i >= K * N) return;
    int k = i / N, n = i - k * N;
    __nv_bfloat16 h, l;
    split_bf16(W[i], h, l);
    hi[(size_t)n * K + k] = h;
    lo[(size_t)n * K + k] = l;
}

// ===========================================================================
// mma.sync-based split-bf16 GEMM (arch-portable HMMA path)
// C[M,N] = A[M,K] @ Bt[N,K]^T;  D += Ah*Bh + Ah*Bl + Al*Bh  (fp32 acc)
// CTA tile 128x128, 8 warps (2x4), warp tile 64x32, K-chunk 64,
// cp.async double-buffered, 144B-padded smem rows (conflict-free ldmatrix).
// EPI: 0 relu(v+bias)->split bf16; 1 v+bias->fp32; 2 (v+bias)*gate->split bf16; 3 v->fp32
// ===========================================================================
__device__ __forceinline__ uint32_t smem_u32(const void* p) {
    uint32_t a;
    asm("{ .reg .u64 t; cvta.to.shared.u64 t, %1; cvt.u32.u64 %0, t; }" : "=r"(a) : "l"(p));
    return a;
}
__device__ __forceinline__ void ldm_x4(unsigned* r, uint32_t addr) {
    asm volatile("ldmatrix.sync.aligned.m8n8.x4.shared.b16 {%0,%1,%2,%3}, [%4];"
                 : "=r"(r[0]), "=r"(r[1]), "=r"(r[2]), "=r"(r[3]) : "r"(addr));
}
__device__ __forceinline__ void mma_bf16(float* d, const unsigned* a, unsigned b0, unsigned b1) {
    asm volatile("mma.sync.aligned.m16n8k16.row.col.f32.bf16.bf16.f32 "
                 "{%0,%1,%2,%3}, {%4,%5,%6,%7}, {%8,%9}, {%0,%1,%2,%3};"
                 : "+f"(d[0]), "+f"(d[1]), "+f"(d[2]), "+f"(d[3])
                 : "r"(a[0]), "r"(a[1]), "r"(a[2]), "r"(a[3]), "r"(b0), "r"(b1));
}
__device__ __forceinline__ void cp16(uint32_t dst, const void* src) {
    asm volatile("cp.async.cg.shared.global [%0], [%1], 16;" :: "r"(dst), "l"(src));
}

#define ROWB 144                     // padded row stride in bytes (64 bf16 + 8 pad)
#define OPB  (128 * ROWB)            // one operand tile: 18432 B
#define STAGEB (4 * OPB)             // Ah, Al, Bh, Bl:    73728 B
static const int DYN_SMEM = 2 * STAGEB;   // 147456 B

template <int EPI>
__global__ void __launch_bounds__(256, 1)
tc_gemm(const __nv_bfloat16* __restrict__ Ahi, const __nv_bfloat16* __restrict__ Alo,
        const __nv_bfloat16* __restrict__ Bhi, const __nv_bfloat16* __restrict__ Blo,
        const float* __restrict__ bias, const float* __restrict__ gate,
        float* __restrict__ outf,
        __nv_bfloat16* __restrict__ ohi, __nv_bfloat16* __restrict__ olo,
        int N, int K) {
    extern __shared__ char smem[];
    const uint32_t sb = smem_u32(smem);
    const int tid = threadIdx.x, wid = tid >> 5, lane = tid & 31;
    const int mbase = blockIdx.y << 7, nbase = blockIdx.x << 7;
    const int wm = (wid & 1) * 64;        // warp M offset in tile
    const int wn = (wid >> 1) * 32;       // warp N offset in tile

    // gmem load geometry: 2 threads/row, 4 x 16B each
    const int lrow = tid >> 1;
    const int lg   = (tid & 1) * 4;       // 16B-group base within 64-elem row
    const __nv_bfloat16* gsrc[4];
    gsrc[0] = Ahi + (size_t)(mbase + lrow) * K + lg * 8;
    gsrc[1] = Alo + (size_t)(mbase + lrow) * K + lg * 8;
    gsrc[2] = Bhi + (size_t)(nbase + lrow) * K + lg * 8;
    gsrc[3] = Blo + (size_t)(nbase + lrow) * K + lg * 8;
    const uint32_t sdst_row = (uint32_t)lrow * ROWB + (uint32_t)lg * 16;

    float acc[4][4][4];
#pragma unroll
    for (int i = 0; i < 4; ++i)
#pragma unroll
        for (int j = 0; j < 4; ++j)
#pragma unroll
            for (int q = 0; q < 4; ++q) acc[i][j][q] = 0.f;

    const int nch = K >> 6;

    // prologue: chunk 0 -> stage 0
#pragma unroll
    for (int op = 0; op < 4; ++op)
#pragma unroll
        for (int i = 0; i < 4; ++i)
            cp16(sb + op * OPB + sdst_row + i * 16, gsrc[op] + i * 8);
    asm volatile("cp.async.commit_group;" ::: "memory");

    // ldmatrix address bases (within an operand tile)
    const uint32_t a_off = (uint32_t)(lane & 15) * ROWB + (uint32_t)(lane >> 4) * 16;

    for (int k = 0; k < nch; ++k) {
        const uint32_t stg = sb + (uint32_t)(k & 1) * STAGEB;
        if (k + 1 < nch) {
            const uint32_t nstg = sb + (uint32_t)((k + 1) & 1) * STAGEB;
            const size_t koff = (size_t)(k + 1) * 64;
#pragma unroll
            for (int op = 0; op < 4; ++op)
#pragma unroll
                for (int i = 0; i < 4; ++i)
                    cp16(nstg + op * OPB + sdst_row + i * 16, gsrc[op] + koff + i * 8);
            asm volatile("cp.async.commit_group;" ::: "memory");
            asm volatile("cp.async.wait_group 1;" ::: "memory");
        } else {
            asm volatile("cp.async.wait_group 0;" ::: "memory");
        }
        __syncthreads();

        const uint32_t ah_b = stg + 0 * OPB + (uint32_t)wm * ROWB + a_off;
        const uint32_t al_b = stg + 1 * OPB + (uint32_t)wm * ROWB + a_off;
        const uint32_t bh_b = stg + 2 * OPB + (uint32_t)wn * ROWB + a_off;
        const uint32_t bl_b = stg + 3 * OPB + (uint32_t)wn * ROWB + a_off;

#pragma unroll
        for (int ks = 0; ks < 4; ++ks) {
            unsigned ah[4][4], al[4][4], bhv[2][4], blv[2][4];
#pragma unroll
            for (int ma = 0; ma < 4; ++ma) {
                ldm_x4(ah[ma], ah_b + (uint32_t)ma * 16 * ROWB + (uint32_t)ks * 32);
                ldm_x4(al[ma], al_b + (uint32_t)ma * 16 * ROWB + (uint32_t)ks * 32);
            }
#pragma unroll
            for (int nb = 0; nb < 2; ++nb) {
                ldm_x4(bhv[nb], bh_b + (uint32_t)nb * 16 * ROWB + (uint32_t)ks * 32);
                ldm_x4(blv[nb], bl_b + (uint32_t)nb * 16 * ROWB + (uint32_t)ks * 32);
            }
            // n-atom na: regs {r0,r2} for even (rows n..n+7), {r1,r3} for odd
#pragma unroll
            for (int ma = 0; ma < 4; ++ma)
#pragma unroll
                for (int na = 0; na < 4; ++na) {
                    unsigned b0h = bhv[na >> 1][na & 1], b1h = bhv[na >> 1][(na & 1) + 2];
                    unsigned b0l = blv[na >> 1][na & 1], b1l = blv[na >> 1][(na & 1) + 2];
                    mma_bf16(acc[ma][na], ah[ma], b0h, b1h);
                    mma_bf16(acc[ma][na], ah[ma], b0l, b1l);
                    mma_bf16(acc[ma][na], al[ma], b0h, b1h);
                }
        }
        __syncthreads();
    }

    // epilogue directly from registers
    const int lr = lane >> 2;
    const int lc = (lane & 3) * 2;
#pragma unroll
    for (int na = 0; na < 4; ++na) {
        const int c = nbase + wn + na * 8 + lc;
        float bx = 0.f, by = 0.f;
        if (EPI == 0 || EPI == 1 || EPI == 2) { bx = bias[c]; by = bias[c + 1]; }
#pragma unroll
        for (int ma = 0; ma < 4; ++ma) {
            const int r = mbase + wm + ma * 16 + lr;
#pragma unroll
            for (int half = 0; half < 2; ++half) {
                const size_t idx = (size_t)(r + half * 8) * N + c;
                float v0 = acc[ma][na][half * 2 + 0];
                float v1 = acc[ma][na][half * 2 + 1];
                if (EPI == 0) {
                    v0 = fmaxf(v0 + bx, 0.f); v1 = fmaxf(v1 + by, 0.f);
                } else if (EPI == 1) {
                    v0 += bx; v1 += by;
                } else if (EPI == 2) {
                    float2 g2 = *reinterpret_cast<const float2*>(gate + idx);
                    v0 = (v0 + bx) * g2.x; v1 = (v1 + by) * g2.y;
                }
                if (EPI == 0 || EPI == 2) {
                    __nv_bfloat16 h0, l0, h1, l1;
                    split_bf16(v0, h0, l0);
                    split_bf16(v1, h1, l1);
                    __nv_bfloat162 hp, lp;
                    hp.x = h0; hp.y = h1; lp.x = l0; lp.y = l1;
                    *reinterpret_cast<__nv_bfloat162*>(ohi + idx) = hp;
                    *reinterpret_cast<__nv_bfloat162*>(olo + idx) = lp;
                } else {
                    float2 o; o.x = v0; o.y = v1;
                    *reinterpret_cast<float2*>(outf + idx) = o;
                }
            }
        }
    }
}

// ===========================================================================
extern "C" void kernel_launch(void* const* d_in, const int* in_sizes, int n_in,
                              void* d_out, int out_size) {
    const float* x    = (const float*)d_in[0];
    const float* van  = (const float*)d_in[1];
    const float* e_sp = (const float*)d_in[2];
    const float* W1e  = (const float*)d_in[3];
    const float* b1e  = (const float*)d_in[4];
    const float* W2e  = (const float*)d_in[5];
    const float* b2e  = (const float*)d_in[6];
    const float* W1r  = (const float*)d_in[7];
    const float* b1r  = (const float*)d_in[8];
    const float* W2r  = (const float*)d_in[9];
    const float* b2r  = (const float*)d_in[10];
    float* out = (float*)d_out;

    __nv_bfloat16 *xh, *xl, *hh, *hl, *ch, *cl, *cth, *ctl, *wth, *wtl;
    float *pe;
    cudaGetSymbolAddress((void**)&xh, g_x_hi);   cudaGetSymbolAddress((void**)&xl, g_x_lo);
    cudaGetSymbolAddress((void**)&hh, g_h_hi);   cudaGetSymbolAddress((void**)&hl, g_h_lo);
    cudaGetSymbolAddress((void**)&ch, g_c_hi);   cudaGetSymbolAddress((void**)&cl, g_c_lo);
    cudaGetSymbolAddress((void**)&cth, g_ct_hi); cudaGetSymbolAddress((void**)&ctl, g_ct_lo);
    cudaGetSymbolAddress((void**)&wth, g_wt_hi); cudaGetSymbolAddress((void**)&wtl, g_wt_lo);
    cudaGetSymbolAddress((void**)&pe, g_e);

    cudaFuncSetAttribute(tc_gemm<0>, cudaFuncAttributeMaxDynamicSharedMemorySize, DYN_SMEM);
    cudaFuncSetAttribute(tc_gemm<1>, cudaFuncAttributeMaxDynamicSharedMemorySize, DYN_SMEM);
    cudaFuncSetAttribute(tc_gemm<2>, cudaFuncAttributeMaxDynamicSharedMemorySize, DYN_SMEM);
    cudaFuncSetAttribute(tc_gemm<3>, cudaFuncAttributeMaxDynamicSharedMemorySize, DYN_SMEM);

    const size_t WSLOT = (size_t)HH * DD;

    cvt_split_kernel<<<(BB * DD + 255) / 256, 256>>>(x, xh, xl, BB * DD);
    wsplit_kernel<<<(DD * HH + 255) / 256, 256>>>(W1e, wth + 0 * WSLOT, wtl + 0 * WSLOT, DD, HH);
    wsplit_kernel<<<(HH * CC + 255) / 256, 256>>>(W2e, wth + 1 * WSLOT, wtl + 1 * WSLOT, HH, CC);
    wsplit_kernel<<<(DD * HH + 255) / 256, 256>>>(W1r, wth + 2 * WSLOT, wtl + 2 * WSLOT, DD, HH);
    wsplit_kernel<<<(HH * CC + 255) / 256, 256>>>(W2r, wth + 3 * WSLOT, wtl + 3 * WSLOT, HH, CC);
    mask_comps_kernel<<<(CC * DD / 2 + 255) / 256, 256>>>(van, e_sp, cth, ctl);

    // energy MLP
    tc_gemm<0><<<dim3(HH / 128, BB / 128), 256, DYN_SMEM>>>(
        xh, xl, wth + 0 * WSLOT, wtl + 0 * WSLOT, b1e, nullptr, nullptr, hh, hl, HH, DD);
    tc_gemm<1><<<dim3(CC / 128, BB / 128), 256, DYN_SMEM>>>(
        hh, hl, wth + 1 * WSLOT, wtl + 1 * WSLOT, b2e, nullptr, pe, nullptr, nullptr, CC, HH);

    // Langevin gate
    gate_kernel<<<(BB * CC / 2 + 255) / 256, 256>>>(pe);

    // regressor MLP + gated epilogue
    tc_gemm<0><<<dim3(HH / 128, BB / 128), 256, DYN_SMEM>>>(
        xh, xl, wth + 2 * WSLOT, wtl + 2 * WSLOT, b1r, nullptr, nullptr, hh, hl, HH, DD);
    tc_gemm<2><<<dim3(CC / 128, BB / 128), 256, DYN_SMEM>>>(
        hh, hl, wth + 3 * WSLOT, wtl + 3 * WSLOT, b2r, pe, nullptr, ch, cl, CC, HH);

    // aggregate
    tc_gemm<3><<<dim3(DD / 128, BB / 128), 256, DYN_SMEM>>>(
        ch, cl, cth, ctl, nullptr, nullptr, out, nullptr, nullptr, DD, CC);
}

// round 5
// speedup vs baseline: 1.4130x; 1.0255x over previous
#include <cuda_runtime.h>
#include <cuda_bf16.h>
#include <cstdint>
#include <math.h>

#define BB 16384
#define CC 512
#define DD 512
#define HH 1024

// ===========================================================================
// JAX threefry2x32 (exact), PARTITIONABLE mode — validated in round 2
// ===========================================================================
struct U2 { unsigned a, b; };

__host__ __device__ constexpr unsigned rotl32(unsigned v, int r) {
    return (v << r) | (v >> (32 - r));
}

__host__ __device__ constexpr U2 tf2x32(unsigned k0, unsigned k1, unsigned x0, unsigned x1) {
    unsigned ks2 = 0x1BD11BDAu ^ k0 ^ k1;
    x0 += k0; x1 += k1;
#define TFR(r) { x0 += x1; x1 = rotl32(x1, (r)); x1 ^= x0; }
    TFR(13) TFR(15) TFR(26) TFR(6)
    x0 += k1;  x1 += ks2 + 1u;
    TFR(17) TFR(29) TFR(16) TFR(24)
    x0 += ks2; x1 += k0 + 2u;
    TFR(13) TFR(15) TFR(26) TFR(6)
    x0 += k0;  x1 += k1 + 3u;
    TFR(17) TFR(29) TFR(16) TFR(24)
    x0 += k1;  x1 += ks2 + 4u;
    TFR(13) TFR(15) TFR(26) TFR(6)
    x0 += ks2; x1 += k0 + 5u;
#undef TFR
    return U2{x0, x1};
}

constexpr U2 ROOT_K1 = tf2x32(0u, 42u, 0u, 0u);
constexpr U2 ROOT_K2 = tf2x32(0u, 42u, 0u, 1u);

struct Step12 { unsigned c[12]; };
struct Tab { Step12 s[32]; };

constexpr Tab make_tab(unsigned K0, unsigned K1) {
    Tab t{};
    for (int i = 0; i < 32; ++i) {
        U2 kp = tf2x32(K0, K1, 0u, (unsigned)i);
        unsigned k0 = kp.a, k1 = kp.b;
        unsigned ks2 = 0x1BD11BDAu ^ k0 ^ k1;
        unsigned* c = t.s[i].c;
        c[0]  = k0;   c[1]  = k1;
        c[2]  = k1;   c[3]  = ks2 + 1u;
        c[4]  = ks2;  c[5]  = k0 + 2u;
        c[6]  = k0;   c[7]  = k1 + 3u;
        c[8]  = k1;   c[9]  = ks2 + 4u;
        c[10] = ks2;  c[11] = k0 + 5u;
    }
    return t;
}

__constant__ Tab TAB_SP  = make_tab(ROOT_K1.a, ROOT_K1.b);
__constant__ Tab TAB_DYN = make_tab(ROOT_K2.a, ROOT_K2.b);

__device__ __forceinline__ unsigned tf_bits(const unsigned* __restrict__ c, unsigned j) {
    unsigned x0 = c[0];
    unsigned x1 = j + c[1];
#define TFR(r) { x0 += x1; x1 = rotl32(x1, (r)); x1 ^= x0; }
    TFR(13) TFR(15) TFR(26) TFR(6)
    x0 += c[2];  x1 += c[3];
    TFR(17) TFR(29) TFR(16) TFR(24)
    x0 += c[4];  x1 += c[5];
    TFR(13) TFR(15) TFR(26) TFR(6)
    x0 += c[6];  x1 += c[7];
    TFR(17) TFR(29) TFR(16) TFR(24)
    x0 += c[8];  x1 += c[9];
    TFR(13) TFR(15) TFR(26) TFR(6)
    x0 += c[10]; x1 += c[11];
#undef TFR
    return x0 ^ x1;
}

__device__ __forceinline__ float normal_from_bits(unsigned bits) {
    float f = __uint_as_float((bits >> 9) | 0x3f800000u) - 1.0f;
    float x = fmaf(f, 1.99999994f, -0.99999994f);
    float w = -__logf(fmaf(x, -x, 1.0f));
    float p;
    if (w < 5.0f) {
        w -= 2.5f;
        p = 2.81022636e-08f;
        p = fmaf(p, w, 3.43273939e-07f);
        p = fmaf(p, w, -3.5233877e-06f);
        p = fmaf(p, w, -4.39150654e-06f);
        p = fmaf(p, w, 0.00021858087f);
        p = fmaf(p, w, -0.00125372503f);
        p = fmaf(p, w, -0.00417768164f);
        p = fmaf(p, w, 0.246640727f);
        p = fmaf(p, w, 1.50140941f);
    } else {
        w = sqrtf(w) - 3.0f;
        p = -0.000200214257f;
        p = fmaf(p, w, 0.000100950558f);
        p = fmaf(p, w, 0.00134934322f);
        p = fmaf(p, w, -0.00367342844f);
        p = fmaf(p, w, 0.00573950773f);
        p = fmaf(p, w, -0.0076224613f);
        p = fmaf(p, w, 0.00943887047f);
        p = fmaf(p, w, 1.00167406f);
        p = fmaf(p, w, 2.83297682f);
    }
    return 1.41421354f * (p * x);
}

// ===========================================================================
// Scratch (device globals)
// ===========================================================================
__device__ __align__(256) __nv_bfloat16 g_x_hi[BB * DD], g_x_lo[BB * DD];
__device__ __align__(256) __nv_bfloat16 g_h_hi[BB * HH], g_h_lo[BB * HH];
__device__ __align__(256) __nv_bfloat16 g_c_hi[BB * CC], g_c_lo[BB * CC];
__device__ __align__(256) __nv_bfloat16 g_ct_hi[DD * CC], g_ct_lo[DD * CC];
__device__ __align__(256) __nv_bfloat16 g_wt_hi[4 * HH * DD], g_wt_lo[4 * HH * DD];
__device__ __align__(256) float g_e[BB * CC];   // e_dyn -> gate (in place)

__device__ __forceinline__ void split_bf16(float v, __nv_bfloat16& h, __nv_bfloat16& l) {
    h = __float2bfloat16_rn(v);
    l = __float2bfloat16_rn(v - __bfloat162float(h));
}

// ===========================================================================
// Langevin gates — 4 elements/thread for ILP; 2-FMA step form
// u_{t+1} = 0.95*u + (-0.05*e + 0.1*n)
// ===========================================================================
__global__ void mask_comps_kernel(const float* __restrict__ vanilla,
                                  const float* __restrict__ e_sp,
                                  __nv_bfloat16* __restrict__ ct_hi,
                                  __nv_bfloat16* __restrict__ ct_lo) {
    const int quarter = (CC * DD) / 4;
    int p0 = blockIdx.x * blockDim.x + threadIdx.x;
    if (p0 >= quarter) return;
    unsigned j = 4u * (unsigned)p0;
    float4 ev = *reinterpret_cast<const float4*>(e_sp + j);
    float et0 = -0.05f * ev.x, et1 = -0.05f * ev.y;
    float et2 = -0.05f * ev.z, et3 = -0.05f * ev.w;
    float u0 = 0.f, u1 = 0.f, u2 = 0.f, u3 = 0.f;
#pragma unroll 1
    for (int t = 0; t < 32; ++t) {
        const unsigned* c = TAB_SP.s[t].c;
        float n0 = normal_from_bits(tf_bits(c, j));
        float n1 = normal_from_bits(tf_bits(c, j + 1u));
        float n2 = normal_from_bits(tf_bits(c, j + 2u));
        float n3 = normal_from_bits(tf_bits(c, j + 3u));
        u0 = fmaf(0.95f, u0, fmaf(0.1f, n0, et0));
        u1 = fmaf(0.95f, u1, fmaf(0.1f, n1, et1));
        u2 = fmaf(0.95f, u2, fmaf(0.1f, n2, et2));
        u3 = fmaf(0.95f, u3, fmaf(0.1f, n3, et3));
    }
    float4 vv = *reinterpret_cast<const float4*>(vanilla + j);
    float v0 = fabsf(vv.x) / (1.f + __expf(u0));
    float v1 = fabsf(vv.y) / (1.f + __expf(u1));
    float v2 = fabsf(vv.z) / (1.f + __expf(u2));
    float v3 = fabsf(vv.w) / (1.f + __expf(u3));
    int c_row = (int)(j >> 9);
    int d_col = (int)(j & 511u);
    __nv_bfloat16 h, l;
    split_bf16(v0, h, l);
    ct_hi[(size_t)d_col * CC + c_row] = h;  ct_lo[(size_t)d_col * CC + c_row] = l;
    split_bf16(v1, h, l);
    ct_hi[(size_t)(d_col + 1) * CC + c_row] = h;  ct_lo[(size_t)(d_col + 1) * CC + c_row] = l;
    split_bf16(v2, h, l);
    ct_hi[(size_t)(d_col + 2) * CC + c_row] = h;  ct_lo[(size_t)(d_col + 2) * CC + c_row] = l;
    split_bf16(v3, h, l);
    ct_hi[(size_t)(d_col + 3) * CC + c_row] = h;  ct_lo[(size_t)(d_col + 3) * CC + c_row] = l;
}

__global__ void gate_kernel(float* __restrict__ e) {
    const int quarter = (BB * CC) / 4;
    int p0 = blockIdx.x * blockDim.x + threadIdx.x;
    if (p0 >= quarter) return;
    unsigned j = 4u * (unsigned)p0;
    float4 ev = *reinterpret_cast<const float4*>(e + j);
    float et0 = -0.05f * ev.x, et1 = -0.05f * ev.y;
    float et2 = -0.05f * ev.z, et3 = -0.05f * ev.w;
    float u0 = 0.f, u1 = 0.f, u2 = 0.f, u3 = 0.f;
#pragma unroll 1
    for (int t = 0; t < 32; ++t) {
        const unsigned* c = TAB_DYN.s[t].c;
        float n0 = normal_from_bits(tf_bits(c, j));
        float n1 = normal_from_bits(tf_bits(c, j + 1u));
        float n2 = normal_from_bits(tf_bits(c, j + 2u));
        float n3 = normal_from_bits(tf_bits(c, j + 3u));
        u0 = fmaf(0.95f, u0, fmaf(0.1f, n0, et0));
        u1 = fmaf(0.95f, u1, fmaf(0.1f, n1, et1));
        u2 = fmaf(0.95f, u2, fmaf(0.1f, n2, et2));
        u3 = fmaf(0.95f, u3, fmaf(0.1f, n3, et3));
    }
    float4 o;
    o.x = 1.f / (1.f + __expf(u0));
    o.y = 1.f / (1.f + __expf(u1));
    o.z = 1.f / (1.f + __expf(u2));
    o.w = 1.f / (1.f + __expf(u3));
    *reinterpret_cast<float4*>(e + j) = o;
}

// ===========================================================================
// conversions (vectorized)
// ===========================================================================
__global__ void cvt_split_kernel(const float* __restrict__ in,
                                 __nv_bfloat16* __restrict__ hi,
                                 __nv_bfloat16* __restrict__ lo, int n_half) {
    int i = blockIdx.x * blockDim.x + threadIdx.x;
    if (i >= n_half) return;
    float2 v = *reinterpret_cast<const float2*>(in + 2 * i);
    __nv_bfloat16 h0, l0, h1, l1;
    split_bf16(v.x, h0, l0);
    split_bf16(v.y, h1, l1);
    __nv_bfloat162 hp, lp;
    hp.x = h0; hp.y = h1; lp.x = l0; lp.y = l1;
    *reinterpret_cast<__nv_bfloat162*>(hi + 2 * i) = hp;
    *reinterpret_cast<__nv_bfloat162*>(lo + 2 * i) = lp;
}

// W [K,N] row-major -> Wt [N,K] split bf16; each thread: 4 consecutive k, one n
__global__ void wsplit_kernel(const float* __restrict__ W,
                              __nv_bfloat16* __restrict__ hi,
                              __nv_bfloat16* __restrict__ lo, int K, int N) {
    int i = blockIdx.x * blockDim.x + threadIdx.x;
    if (i >= (K / 4) * N) return;
    int n = i % N;
    int k4 = (i / N) * 4;
    __nv_bfloat16 h[4], l[4];
#pragma unroll
    for (int q = 0; q < 4; ++q)
        split_bf16(W[(size_t)(k4 + q) * N + n], h[q], l[q]);
    __nv_bfloat162 hp0, hp1, lp0, lp1;
    hp0.x = h[0]; hp0.y = h[1]; hp1.x = h[2]; hp1.y = h[3];
    lp0.x = l[0]; lp0.y = l[1]; lp1.x = l[2]; lp1.y = l[3];
    size_t o = (size_t)n * K + k4;
    *reinterpret_cast<__nv_bfloat162*>(hi + o)     = hp0;
    *reinterpret_cast<__nv_bfloat162*>(hi + o + 2) = hp1;
    *reinterpret_cast<__nv_bfloat162*>(lo + o)     = lp0;
    *reinterpret_cast<__nv_bfloat162*>(lo + o + 2) = lp1;
}

// ===========================================================================
// mma.sync split-bf16 GEMM, pass-major mainloop (no accumulator RAW chains)
// ===========================================================================
__device__ __forceinline__ uint32_t smem_u32(const void* p) {
    uint32_t a;
    asm("{ .reg .u64 t; cvta.to.shared.u64 t, %1; cvt.u32.u64 %0, t; }" : "=r"(a) : "l"(p));
    return a;
}
__device__ __forceinline__ void ldm_x4(unsigned* r, uint32_t addr) {
    asm volatile("ldmatrix.sync.aligned.m8n8.x4.shared.b16 {%0,%1,%2,%3}, [%4];"
                 : "=r"(r[0]), "=r"(r[1]), "=r"(r[2]), "=r"(r[3]) : "r"(addr));
}
__device__ __forceinline__ void mma_bf16(float* d, const unsigned* a, unsigned b0, unsigned b1) {
    asm volatile("mma.sync.aligned.m16n8k16.row.col.f32.bf16.bf16.f32 "
                 "{%0,%1,%2,%3}, {%4,%5,%6,%7}, {%8,%9}, {%0,%1,%2,%3};"
                 : "+f"(d[0]), "+f"(d[1]), "+f"(d[2]), "+f"(d[3])
                 : "r"(a[0]), "r"(a[1]), "r"(a[2]), "r"(a[3]), "r"(b0), "r"(b1));
}
__device__ __forceinline__ void cp16(uint32_t dst, const void* src) {
    asm volatile("cp.async.cg.shared.global [%0], [%1], 16;" :: "r"(dst), "l"(src));
}

#define ROWB 144
#define OPB  (128 * ROWB)
#define STAGEB (4 * OPB)
static const int DYN_SMEM = 2 * STAGEB;   // 147456 B

template <int EPI>
__global__ void __launch_bounds__(256, 1)
tc_gemm(const __nv_bfloat16* __restrict__ Ahi, const __nv_bfloat16* __restrict__ Alo,
        const __nv_bfloat16* __restrict__ Bhi, const __nv_bfloat16* __restrict__ Blo,
        const float* __restrict__ bias, const float* __restrict__ gate,
        float* __restrict__ outf,
        __nv_bfloat16* __restrict__ ohi, __nv_bfloat16* __restrict__ olo,
        int N, int K) {
    extern __shared__ char smem[];
    const uint32_t sb = smem_u32(smem);
    const int tid = threadIdx.x, wid = tid >> 5, lane = tid & 31;
    const int mbase = blockIdx.y << 7, nbase = blockIdx.x << 7;
    const int wm = (wid & 1) * 64;
    const int wn = (wid >> 1) * 32;

    const int lrow = tid >> 1;
    const int lg   = (tid & 1) * 4;
    const __nv_bfloat16* gsrc[4];
    gsrc[0] = Ahi + (size_t)(mbase + lrow) * K + lg * 8;
    gsrc[1] = Alo + (size_t)(mbase + lrow) * K + lg * 8;
    gsrc[2] = Bhi + (size_t)(nbase + lrow) * K + lg * 8;
    gsrc[3] = Blo + (size_t)(nbase + lrow) * K + lg * 8;
    const uint32_t sdst_row = (uint32_t)lrow * ROWB + (uint32_t)lg * 16;

    float acc[4][4][4];
#pragma unroll
    for (int i = 0; i < 4; ++i)
#pragma unroll
        for (int j = 0; j < 4; ++j)
#pragma unroll
            for (int q = 0; q < 4; ++q) acc[i][j][q] = 0.f;

    const int nch = K >> 6;

#pragma unroll
    for (int op = 0; op < 4; ++op)
#pragma unroll
        for (int i = 0; i < 4; ++i)
            cp16(sb + op * OPB + sdst_row + i * 16, gsrc[op] + i * 8);
    asm volatile("cp.async.commit_group;" ::: "memory");

    const uint32_t a_off = (uint32_t)(lane & 15) * ROWB + (uint32_t)(lane >> 4) * 16;

    for (int k = 0; k < nch; ++k) {
        const uint32_t stg = sb + (uint32_t)(k & 1) * STAGEB;
        if (k + 1 < nch) {
            const uint32_t nstg = sb + (uint32_t)((k + 1) & 1) * STAGEB;
            const size_t koff = (size_t)(k + 1) * 64;
#pragma unroll
            for (int op = 0; op < 4; ++op)
#pragma unroll
                for (int i = 0; i < 4; ++i)
                    cp16(nstg + op * OPB + sdst_row + i * 16, gsrc[op] + koff + i * 8);
            asm volatile("cp.async.commit_group;" ::: "memory");
            asm volatile("cp.async.wait_group 1;" ::: "memory");
        } else {
            asm volatile("cp.async.wait_group 0;" ::: "memory");
        }
        __syncthreads();

        const uint32_t ah_b = stg + 0 * OPB + (uint32_t)wm * ROWB + a_off;
        const uint32_t al_b = stg + 1 * OPB + (uint32_t)wm * ROWB + a_off;
        const uint32_t bh_b = stg + 2 * OPB + (uint32_t)wn * ROWB + a_off;
        const uint32_t bl_b = stg + 3 * OPB + (uint32_t)wn * ROWB + a_off;

#pragma unroll
        for (int ks = 0; ks < 4; ++ks) {
            unsigned ah[4][4], al[4][4], bhv[2][4], blv[2][4];
#pragma unroll
            for (int ma = 0; ma < 4; ++ma) {
                ldm_x4(ah[ma], ah_b + (uint32_t)ma * 16 * ROWB + (uint32_t)ks * 32);
                ldm_x4(al[ma], al_b + (uint32_t)ma * 16 * ROWB + (uint32_t)ks * 32);
            }
#pragma unroll
            for (int nb = 0; nb < 2; ++nb) {
                ldm_x4(bhv[nb], bh_b + (uint32_t)nb * 16 * ROWB + (uint32_t)ks * 32);
                ldm_x4(blv[nb], bl_b + (uint32_t)nb * 16 * ROWB + (uint32_t)ks * 32);
            }
            // pass-major: 16 independent MMAs between successive writes to the
            // same accumulator; per-acc accumulation order (hh, hl, lh) unchanged
#pragma unroll
            for (int ma = 0; ma < 4; ++ma)
#pragma unroll
                for (int na = 0; na < 4; ++na)
                    mma_bf16(acc[ma][na], ah[ma],
                             bhv[na >> 1][na & 1], bhv[na >> 1][(na & 1) + 2]);
#pragma unroll
            for (int ma = 0; ma < 4; ++ma)
#pragma unroll
                for (int na = 0; na < 4; ++na)
                    mma_bf16(acc[ma][na], ah[ma],
                             blv[na >> 1][na & 1], blv[na >> 1][(na & 1) + 2]);
#pragma unroll
            for (int ma = 0; ma < 4; ++ma)
#pragma unroll
                for (int na = 0; na < 4; ++na)
                    mma_bf16(acc[ma][na], al[ma],
                             bhv[na >> 1][na & 1], bhv[na >> 1][(na & 1) + 2]);
        }
        __syncthreads();
    }

    const int lr = lane >> 2;
    const int lc = (lane & 3) * 2;
#pragma unroll
    for (int na = 0; na < 4; ++na) {
        const int c = nbase + wn + na * 8 + lc;
        float bx = 0.f, by = 0.f;
        if (EPI == 0 || EPI == 1 || EPI == 2) { bx = bias[c]; by = bias[c + 1]; }
#pragma unroll
        for (int ma = 0; ma < 4; ++ma) {
            const int r = mbase + wm + ma * 16 + lr;
#pragma unroll
            for (int half = 0; half < 2; ++half) {
                const size_t idx = (size_t)(r + half * 8) * N + c;
                float v0 = acc[ma][na][half * 2 + 0];
                float v1 = acc[ma][na][half * 2 + 1];
                if (EPI == 0) {
                    v0 = fmaxf(v0 + bx, 0.f); v1 = fmaxf(v1 + by, 0.f);
                } else if (EPI == 1) {
                    v0 += bx; v1 += by;
                } else if (EPI == 2) {
                    float2 g2 = *reinterpret_cast<const float2*>(gate + idx);
                    v0 = (v0 + bx) * g2.x; v1 = (v1 + by) * g2.y;
                }
                if (EPI == 0 || EPI == 2) {
                    __nv_bfloat16 h0, l0, h1, l1;
                    split_bf16(v0, h0, l0);
                    split_bf16(v1, h1, l1);
                    __nv_bfloat162 hp, lp;
                    hp.x = h0; hp.y = h1; lp.x = l0; lp.y = l1;
                    *reinterpret_cast<__nv_bfloat162*>(ohi + idx) = hp;
                    *reinterpret_cast<__nv_bfloat162*>(olo + idx) = lp;
                } else {
                    float2 o; o.x = v0; o.y = v1;
                    *reinterpret_cast<float2*>(outf + idx) = o;
                }
            }
        }
    }
}

// ===========================================================================
extern "C" void kernel_launch(void* const* d_in, const int* in_sizes, int n_in,
                              void* d_out, int out_size) {
    const float* x    = (const float*)d_in[0];
    const float* van  = (const float*)d_in[1];
    const float* e_sp = (const float*)d_in[2];
    const float* W1e  = (const float*)d_in[3];
    const float* b1e  = (const float*)d_in[4];
    const float* W2e  = (const float*)d_in[5];
    const float* b2e  = (const float*)d_in[6];
    const float* W1r  = (const float*)d_in[7];
    const float* b1r  = (const float*)d_in[8];
    const float* W2r  = (const float*)d_in[9];
    const float* b2r  = (const float*)d_in[10];
    float* out = (float*)d_out;

    __nv_bfloat16 *xh, *xl, *hh, *hl, *ch, *cl, *cth, *ctl, *wth, *wtl;
    float *pe;
    cudaGetSymbolAddress((void**)&xh, g_x_hi);   cudaGetSymbolAddress((void**)&xl, g_x_lo);
    cudaGetSymbolAddress((void**)&hh, g_h_hi);   cudaGetSymbolAddress((void**)&hl, g_h_lo);
    cudaGetSymbolAddress((void**)&ch, g_c_hi);   cudaGetSymbolAddress((void**)&cl, g_c_lo);
    cudaGetSymbolAddress((void**)&cth, g_ct_hi); cudaGetSymbolAddress((void**)&ctl, g_ct_lo);
    cudaGetSymbolAddress((void**)&wth, g_wt_hi); cudaGetSymbolAddress((void**)&wtl, g_wt_lo);
    cudaGetSymbolAddress((void**)&pe, g_e);

    cudaFuncSetAttribute(tc_gemm<0>, cudaFuncAttributeMaxDynamicSharedMemorySize, DYN_SMEM);
    cudaFuncSetAttribute(tc_gemm<1>, cudaFuncAttributeMaxDynamicSharedMemorySize, DYN_SMEM);
    cudaFuncSetAttribute(tc_gemm<2>, cudaFuncAttributeMaxDynamicSharedMemorySize, DYN_SMEM);
    cudaFuncSetAttribute(tc_gemm<3>, cudaFuncAttributeMaxDynamicSharedMemorySize, DYN_SMEM);

    const size_t WSLOT = (size_t)HH * DD;

    cvt_split_kernel<<<(BB * DD / 2 + 255) / 256, 256>>>(x, xh, xl, BB * DD / 2);
    wsplit_kernel<<<(DD / 4 * HH + 255) / 256, 256>>>(W1e, wth + 0 * WSLOT, wtl + 0 * WSLOT, DD, HH);
    wsplit_kernel<<<(HH / 4 * CC + 255) / 256, 256>>>(W2e, wth + 1 * WSLOT, wtl + 1 * WSLOT, HH, CC);
    wsplit_kernel<<<(DD / 4 * HH + 255) / 256, 256>>>(W1r, wth + 2 * WSLOT, wtl + 2 * WSLOT, DD, HH);
    wsplit_kernel<<<(HH / 4 * CC + 255) / 256, 256>>>(W2r, wth + 3 * WSLOT, wtl + 3 * WSLOT, HH, CC);
    mask_comps_kernel<<<(CC * DD / 4 + 255) / 256, 256>>>(van, e_sp, cth, ctl);

    // energy MLP
    tc_gemm<0><<<dim3(HH / 128, BB / 128), 256, DYN_SMEM>>>(
        xh, xl, wth + 0 * WSLOT, wtl + 0 * WSLOT, b1e, nullptr, nullptr, hh, hl, HH, DD);
    tc_gemm<1><<<dim3(CC / 128, BB / 128), 256, DYN_SMEM>>>(
        hh, hl, wth + 1 * WSLOT, wtl + 1 * WSLOT, b2e, nullptr, pe, nullptr, nullptr, CC, HH);

    // Langevin gate
    gate_kernel<<<(BB * CC / 4 + 255) / 256, 256>>>(pe);

    // regressor MLP + gated epilogue
    tc_gemm<0><<<dim3(HH / 128, BB / 128), 256, DYN_SMEM>>>(
        xh, xl, wth + 2 * WSLOT, wtl + 2 * WSLOT, b1r, nullptr, nullptr, hh, hl, HH, DD);
    tc_gemm<2><<<dim3(CC / 128, BB / 128), 256, DYN_SMEM>>>(
        hh, hl, wth + 3 * WSLOT, wtl + 3 * WSLOT, b2r, pe, nullptr, ch, cl, CC, HH);

    // aggregate
    tc_gemm<3><<<dim3(DD / 128, BB / 128), 256, DYN_SMEM>>>(
        ch, cl, cth, ctl, nullptr, nullptr, out, nullptr, nullptr, DD, CC);
}

// round 6
// speedup vs baseline: 2.1139x; 1.4961x over previous
#include <cuda_runtime.h>
#include <cuda_fp16.h>
#include <cstdint>
#include <math.h>

#define BB 16384
#define CC 512
#define DD 512
#define HH 1024

// ===========================================================================
// JAX threefry2x32 (exact), PARTITIONABLE mode — validated in round 2
// ===========================================================================
struct U2 { unsigned a, b; };

__host__ __device__ constexpr unsigned rotl32(unsigned v, int r) {
    return (v << r) | (v >> (32 - r));
}

__host__ __device__ constexpr U2 tf2x32(unsigned k0, unsigned k1, unsigned x0, unsigned x1) {
    unsigned ks2 = 0x1BD11BDAu ^ k0 ^ k1;
    x0 += k0; x1 += k1;
#define TFR(r) { x0 += x1; x1 = rotl32(x1, (r)); x1 ^= x0; }
    TFR(13) TFR(15) TFR(26) TFR(6)
    x0 += k1;  x1 += ks2 + 1u;
    TFR(17) TFR(29) TFR(16) TFR(24)
    x0 += ks2; x1 += k0 + 2u;
    TFR(13) TFR(15) TFR(26) TFR(6)
    x0 += k0;  x1 += k1 + 3u;
    TFR(17) TFR(29) TFR(16) TFR(24)
    x0 += k1;  x1 += ks2 + 4u;
    TFR(13) TFR(15) TFR(26) TFR(6)
    x0 += ks2; x1 += k0 + 5u;
#undef TFR
    return U2{x0, x1};
}

constexpr U2 ROOT_K1 = tf2x32(0u, 42u, 0u, 0u);
constexpr U2 ROOT_K2 = tf2x32(0u, 42u, 0u, 1u);

struct Step12 { unsigned c[12]; };
struct Tab { Step12 s[32]; };

constexpr Tab make_tab(unsigned K0, unsigned K1) {
    Tab t{};
    for (int i = 0; i < 32; ++i) {
        U2 kp = tf2x32(K0, K1, 0u, (unsigned)i);
        unsigned k0 = kp.a, k1 = kp.b;
        unsigned ks2 = 0x1BD11BDAu ^ k0 ^ k1;
        unsigned* c = t.s[i].c;
        c[0]  = k0;   c[1]  = k1;
        c[2]  = k1;   c[3]  = ks2 + 1u;
        c[4]  = ks2;  c[5]  = k0 + 2u;
        c[6]  = k0;   c[7]  = k1 + 3u;
        c[8]  = k1;   c[9]  = ks2 + 4u;
        c[10] = ks2;  c[11] = k0 + 5u;
    }
    return t;
}

__constant__ Tab TAB_SP  = make_tab(ROOT_K1.a, ROOT_K1.b);
__constant__ Tab TAB_DYN = make_tab(ROOT_K2.a, ROOT_K2.b);

__device__ __forceinline__ unsigned tf_bits(const unsigned* __restrict__ c, unsigned j) {
    unsigned x0 = c[0];
    unsigned x1 = j + c[1];
#define TFR(r) { x0 += x1; x1 = rotl32(x1, (r)); x1 ^= x0; }
    TFR(13) TFR(15) TFR(26) TFR(6)
    x0 += c[2];  x1 += c[3];
    TFR(17) TFR(29) TFR(16) TFR(24)
    x0 += c[4];  x1 += c[5];
    TFR(13) TFR(15) TFR(26) TFR(6)
    x0 += c[6];  x1 += c[7];
    TFR(17) TFR(29) TFR(16) TFR(24)
    x0 += c[8];  x1 += c[9];
    TFR(13) TFR(15) TFR(26) TFR(6)
    x0 += c[10]; x1 += c[11];
#undef TFR
    return x0 ^ x1;
}

__device__ __forceinline__ float normal_from_bits(unsigned bits) {
    float f = __uint_as_float((bits >> 9) | 0x3f800000u) - 1.0f;
    float x = fmaf(f, 1.99999994f, -0.99999994f);
    float w = -__logf(fmaf(x, -x, 1.0f));
    float p;
    if (w < 5.0f) {
        w -= 2.5f;
        p = 2.81022636e-08f;
        p = fmaf(p, w, 3.43273939e-07f);
        p = fmaf(p, w, -3.5233877e-06f);
        p = fmaf(p, w, -4.39150654e-06f);
        p = fmaf(p, w, 0.00021858087f);
        p = fmaf(p, w, -0.00125372503f);
        p = fmaf(p, w, -0.00417768164f);
        p = fmaf(p, w, 0.246640727f);
        p = fmaf(p, w, 1.50140941f);
    } else {
        w = sqrtf(w) - 3.0f;
        p = -0.000200214257f;
        p = fmaf(p, w, 0.000100950558f);
        p = fmaf(p, w, 0.00134934322f);
        p = fmaf(p, w, -0.00367342844f);
        p = fmaf(p, w, 0.00573950773f);
        p = fmaf(p, w, -0.0076224613f);
        p = fmaf(p, w, 0.00943887047f);
        p = fmaf(p, w, 1.00167406f);
        p = fmaf(p, w, 2.83297682f);
    }
    return 1.41421354f * (p * x);
}

// ===========================================================================
// Scratch (device globals) — fp16 single-precision-per-operand path
// ===========================================================================
__device__ __align__(256) __half g_x[BB * DD];        // x fp16
__device__ __align__(256) __half g_h[BB * HH];        // hidden fp16 (reused)
__device__ __align__(256) __half g_c[BB * CC];        // conc*gate fp16
__device__ __align__(256) __half g_ct[DD * CC];       // comps^T fp16
__device__ __align__(256) __half g_wt[4 * HH * DD];   // transposed weights fp16
__device__ __align__(256) float  g_e[BB * CC];        // e_dyn -> gate (in place)

// ===========================================================================
// Langevin gates — 4 elements/thread; u_{t+1} = 0.95*u + (-0.05*e + 0.1*n)
// ===========================================================================
__global__ void mask_comps_kernel(const float* __restrict__ vanilla,
                                  const float* __restrict__ e_sp,
                                  __half* __restrict__ ct) {
    const int quarter = (CC * DD) / 4;
    int p0 = blockIdx.x * blockDim.x + threadIdx.x;
    if (p0 >= quarter) return;
    unsigned j = 4u * (unsigned)p0;
    float4 ev = *reinterpret_cast<const float4*>(e_sp + j);
    float et0 = -0.05f * ev.x, et1 = -0.05f * ev.y;
    float et2 = -0.05f * ev.z, et3 = -0.05f * ev.w;
    float u0 = 0.f, u1 = 0.f, u2 = 0.f, u3 = 0.f;
#pragma unroll 1
    for (int t = 0; t < 32; ++t) {
        const unsigned* c = TAB_SP.s[t].c;
        float n0 = normal_from_bits(tf_bits(c, j));
        float n1 = normal_from_bits(tf_bits(c, j + 1u));
        float n2 = normal_from_bits(tf_bits(c, j + 2u));
        float n3 = normal_from_bits(tf_bits(c, j + 3u));
        u0 = fmaf(0.95f, u0, fmaf(0.1f, n0, et0));
        u1 = fmaf(0.95f, u1, fmaf(0.1f, n1, et1));
        u2 = fmaf(0.95f, u2, fmaf(0.1f, n2, et2));
        u3 = fmaf(0.95f, u3, fmaf(0.1f, n3, et3));
    }
    float4 vv = *reinterpret_cast<const float4*>(vanilla + j);
    float v0 = fabsf(vv.x) / (1.f + __expf(u0));
    float v1 = fabsf(vv.y) / (1.f + __expf(u1));
    float v2 = fabsf(vv.z) / (1.f + __expf(u2));
    float v3 = fabsf(vv.w) / (1.f + __expf(u3));
    int c_row = (int)(j >> 9);
    int d_col = (int)(j & 511u);
    ct[(size_t)(d_col + 0) * CC + c_row] = __float2half_rn(v0);
    ct[(size_t)(d_col + 1) * CC + c_row] = __float2half_rn(v1);
    ct[(size_t)(d_col + 2) * CC + c_row] = __float2half_rn(v2);
    ct[(size_t)(d_col + 3) * CC + c_row] = __float2half_rn(v3);
}

__global__ void gate_kernel(float* __restrict__ e) {
    const int quarter = (BB * CC) / 4;
    int p0 = blockIdx.x * blockDim.x + threadIdx.x;
    if (p0 >= quarter) return;
    unsigned j = 4u * (unsigned)p0;
    float4 ev = *reinterpret_cast<const float4*>(e + j);
    float et0 = -0.05f * ev.x, et1 = -0.05f * ev.y;
    float et2 = -0.05f * ev.z, et3 = -0.05f * ev.w;
    float u0 = 0.f, u1 = 0.f, u2 = 0.f, u3 = 0.f;
#pragma unroll 1
    for (int t = 0; t < 32; ++t) {
        const unsigned* c = TAB_DYN.s[t].c;
        float n0 = normal_from_bits(tf_bits(c, j));
        float n1 = normal_from_bits(tf_bits(c, j + 1u));
        float n2 = normal_from_bits(tf_bits(c, j + 2u));
        float n3 = normal_from_bits(tf_bits(c, j + 3u));
        u0 = fmaf(0.95f, u0, fmaf(0.1f, n0, et0));
        u1 = fmaf(0.95f, u1, fmaf(0.1f, n1, et1));
        u2 = fmaf(0.95f, u2, fmaf(0.1f, n2, et2));
        u3 = fmaf(0.95f, u3, fmaf(0.1f, n3, et3));
    }
    float4 o;
    o.x = 1.f / (1.f + __expf(u0));
    o.y = 1.f / (1.f + __expf(u1));
    o.z = 1.f / (1.f + __expf(u2));
    o.w = 1.f / (1.f + __expf(u3));
    *reinterpret_cast<float4*>(e + j) = o;
}

// ===========================================================================
// conversions
// ===========================================================================
__global__ void cvt_half_kernel(const float* __restrict__ in,
                                __half* __restrict__ out, int n_quarter) {
    int i = blockIdx.x * blockDim.x + threadIdx.x;
    if (i >= n_quarter) return;
    float4 v = *reinterpret_cast<const float4*>(in + 4 * i);
    __half2 p0, p1;
    p0 = __floats2half2_rn(v.x, v.y);
    p1 = __floats2half2_rn(v.z, v.w);
    *reinterpret_cast<__half2*>(out + 4 * i)     = p0;
    *reinterpret_cast<__half2*>(out + 4 * i + 2) = p1;
}

// W [K,N] row-major -> Wt [N,K] fp16; each thread: 4 consecutive k, one n
__global__ void wcvt_kernel(const float* __restrict__ W,
                            __half* __restrict__ o, int K, int N) {
    int i = blockIdx.x * blockDim.x + threadIdx.x;
    if (i >= (K / 4) * N) return;
    int n = i % N;
    int k4 = (i / N) * 4;
    __half2 p0 = __floats2half2_rn(W[(size_t)(k4 + 0) * N + n], W[(size_t)(k4 + 1) * N + n]);
    __half2 p1 = __floats2half2_rn(W[(size_t)(k4 + 2) * N + n], W[(size_t)(k4 + 3) * N + n]);
    size_t off = (size_t)n * K + k4;
    *reinterpret_cast<__half2*>(o + off)     = p0;
    *reinterpret_cast<__half2*>(o + off + 2) = p1;
}

// ===========================================================================
// Single-pass fp16 GEMM (fp32 accumulate): C[M,N] = A[M,K] @ Bt[N,K]^T
// CTA tile 128x128, 8 warps (2x4), warp tile 64x32, K-chunk 64,
// cp.async double-buffered, 144B padded rows.
// EPI: 0 relu(v+bias)->fp16; 1 v+bias->fp32; 2 (v+bias)*gate->fp16; 3 v->fp32
// ===========================================================================
__device__ __forceinline__ uint32_t smem_u32(const void* p) {
    uint32_t a;
    asm("{ .reg .u64 t; cvta.to.shared.u64 t, %1; cvt.u32.u64 %0, t; }" : "=r"(a) : "l"(p));
    return a;
}
__device__ __forceinline__ void ldm_x4(unsigned* r, uint32_t addr) {
    asm volatile("ldmatrix.sync.aligned.m8n8.x4.shared.b16 {%0,%1,%2,%3}, [%4];"
                 : "=r"(r[0]), "=r"(r[1]), "=r"(r[2]), "=r"(r[3]) : "r"(addr));
}
__device__ __forceinline__ void mma_fp16(float* d, const unsigned* a, unsigned b0, unsigned b1) {
    asm volatile("mma.sync.aligned.m16n8k16.row.col.f32.f16.f16.f32 "
                 "{%0,%1,%2,%3}, {%4,%5,%6,%7}, {%8,%9}, {%0,%1,%2,%3};"
                 : "+f"(d[0]), "+f"(d[1]), "+f"(d[2]), "+f"(d[3])
                 : "r"(a[0]), "r"(a[1]), "r"(a[2]), "r"(a[3]), "r"(b0), "r"(b1));
}
__device__ __forceinline__ void cp16(uint32_t dst, const void* src) {
    asm volatile("cp.async.cg.shared.global [%0], [%1], 16;" :: "r"(dst), "l"(src));
}

#define ROWB 144
#define OPB  (128 * ROWB)            // one operand tile: 18432 B
#define STAGEB (2 * OPB)             // A + B per stage:  36864 B
static const int DYN_SMEM = 2 * STAGEB;   // 73728 B (2 CTAs/SM possible)

template <int EPI>
__global__ void __launch_bounds__(256, 2)
tc_gemm(const __half* __restrict__ A, const __half* __restrict__ B,
        const float* __restrict__ bias, const float* __restrict__ gate,
        float* __restrict__ outf, __half* __restrict__ outh,
        int N, int K) {
    extern __shared__ char smem[];
    const uint32_t sb = smem_u32(smem);
    const int tid = threadIdx.x, wid = tid >> 5, lane = tid & 31;
    const int mbase = blockIdx.y << 7, nbase = blockIdx.x << 7;
    const int wm = (wid & 1) * 64;
    const int wn = (wid >> 1) * 32;

    const int lrow = tid >> 1;
    const int lg   = (tid & 1) * 4;
    const __half* gsrcA = A + (size_t)(mbase + lrow) * K + lg * 8;
    const __half* gsrcB = B + (size_t)(nbase + lrow) * K + lg * 8;
    const uint32_t sdst_row = (uint32_t)lrow * ROWB + (uint32_t)lg * 16;

    float acc[4][4][4];
#pragma unroll
    for (int i = 0; i < 4; ++i)
#pragma unroll
        for (int j = 0; j < 4; ++j)
#pragma unroll
            for (int q = 0; q < 4; ++q) acc[i][j][q] = 0.f;

    const int nch = K >> 6;

#pragma unroll
    for (int i = 0; i < 4; ++i) {
        cp16(sb + 0 * OPB + sdst_row + i * 16, gsrcA + i * 8);
        cp16(sb + 1 * OPB + sdst_row + i * 16, gsrcB + i * 8);
    }
    asm volatile("cp.async.commit_group;" ::: "memory");

    const uint32_t a_off = (uint32_t)(lane & 15) * ROWB + (uint32_t)(lane >> 4) * 16;

    for (int k = 0; k < nch; ++k) {
        const uint32_t stg = sb + (uint32_t)(k & 1) * STAGEB;
        if (k + 1 < nch) {
            const uint32_t nstg = sb + (uint32_t)((k + 1) & 1) * STAGEB;
            const size_t koff = (size_t)(k + 1) * 64;
#pragma unroll
            for (int i = 0; i < 4; ++i) {
                cp16(nstg + 0 * OPB + sdst_row + i * 16, gsrcA + koff + i * 8);
                cp16(nstg + 1 * OPB + sdst_row + i * 16, gsrcB + koff + i * 8);
            }
            asm volatile("cp.async.commit_group;" ::: "memory");
            asm volatile("cp.async.wait_group 1;" ::: "memory");
        } else {
            asm volatile("cp.async.wait_group 0;" ::: "memory");
        }
        __syncthreads();

        const uint32_t a_b = stg + 0 * OPB + (uint32_t)wm * ROWB + a_off;
        const uint32_t b_b = stg + 1 * OPB + (uint32_t)wn * ROWB + a_off;

#pragma unroll
        for (int ks = 0; ks < 4; ++ks) {
            unsigned av[4][4], bv[2][4];
#pragma unroll
            for (int ma = 0; ma < 4; ++ma)
                ldm_x4(av[ma], a_b + (uint32_t)ma * 16 * ROWB + (uint32_t)ks * 32);
#pragma unroll
            for (int nb = 0; nb < 2; ++nb)
                ldm_x4(bv[nb], b_b + (uint32_t)nb * 16 * ROWB + (uint32_t)ks * 32);
#pragma unroll
            for (int ma = 0; ma < 4; ++ma)
#pragma unroll
                for (int na = 0; na < 4; ++na)
                    mma_fp16(acc[ma][na], av[ma],
                             bv[na >> 1][na & 1], bv[na >> 1][(na & 1) + 2]);
        }
        __syncthreads();
    }

    const int lr = lane >> 2;
    const int lc = (lane & 3) * 2;
#pragma unroll
    for (int na = 0; na < 4; ++na) {
        const int c = nbase + wn + na * 8 + lc;
        float bx = 0.f, by = 0.f;
        if (EPI == 0 || EPI == 1 || EPI == 2) { bx = bias[c]; by = bias[c + 1]; }
#pragma unroll
        for (int ma = 0; ma < 4; ++ma) {
            const int r = mbase + wm + ma * 16 + lr;
#pragma unroll
            for (int half = 0; half < 2; ++half) {
                const size_t idx = (size_t)(r + half * 8) * N + c;
                float v0 = acc[ma][na][half * 2 + 0];
                float v1 = acc[ma][na][half * 2 + 1];
                if (EPI == 0) {
                    v0 = fmaxf(v0 + bx, 0.f); v1 = fmaxf(v1 + by, 0.f);
                } else if (EPI == 1) {
                    v0 += bx; v1 += by;
                } else if (EPI == 2) {
                    float2 g2 = *reinterpret_cast<const float2*>(gate + idx);
                    v0 = (v0 + bx) * g2.x; v1 = (v1 + by) * g2.y;
                }
                if (EPI == 0 || EPI == 2) {
                    *reinterpret_cast<__half2*>(outh + idx) = __floats2half2_rn(v0, v1);
                } else {
                    float2 o; o.x = v0; o.y = v1;
                    *reinterpret_cast<float2*>(outf + idx) = o;
                }
            }
        }
    }
}

// ===========================================================================
extern "C" void kernel_launch(void* const* d_in, const int* in_sizes, int n_in,
                              void* d_out, int out_size) {
    const float* x    = (const float*)d_in[0];
    const float* van  = (const float*)d_in[1];
    const float* e_sp = (const float*)d_in[2];
    const float* W1e  = (const float*)d_in[3];
    const float* b1e  = (const float*)d_in[4];
    const float* W2e  = (const float*)d_in[5];
    const float* b2e  = (const float*)d_in[6];
    const float* W1r  = (const float*)d_in[7];
    const float* b1r  = (const float*)d_in[8];
    const float* W2r  = (const float*)d_in[9];
    const float* b2r  = (const float*)d_in[10];
    float* out = (float*)d_out;

    __half *px, *ph, *pc, *pct, *pwt;
    float *pe;
    cudaGetSymbolAddress((void**)&px, g_x);
    cudaGetSymbolAddress((void**)&ph, g_h);
    cudaGetSymbolAddress((void**)&pc, g_c);
    cudaGetSymbolAddress((void**)&pct, g_ct);
    cudaGetSymbolAddress((void**)&pwt, g_wt);
    cudaGetSymbolAddress((void**)&pe, g_e);

    cudaFuncSetAttribute(tc_gemm<0>, cudaFuncAttributeMaxDynamicSharedMemorySize, DYN_SMEM);
    cudaFuncSetAttribute(tc_gemm<1>, cudaFuncAttributeMaxDynamicSharedMemorySize, DYN_SMEM);
    cudaFuncSetAttribute(tc_gemm<2>, cudaFuncAttributeMaxDynamicSharedMemorySize, DYN_SMEM);
    cudaFuncSetAttribute(tc_gemm<3>, cudaFuncAttributeMaxDynamicSharedMemorySize, DYN_SMEM);

    const size_t WSLOT = (size_t)HH * DD;

    cvt_half_kernel<<<(BB * DD / 4 + 255) / 256, 256>>>(x, px, BB * DD / 4);
    wcvt_kernel<<<(DD / 4 * HH + 255) / 256, 256>>>(W1e, pwt + 0 * WSLOT, DD, HH);
    wcvt_kernel<<<(HH / 4 * CC + 255) / 256, 256>>>(W2e, pwt + 1 * WSLOT, HH, CC);
    wcvt_kernel<<<(DD / 4 * HH + 255) / 256, 256>>>(W1r, pwt + 2 * WSLOT, DD, HH);
    wcvt_kernel<<<(HH / 4 * CC + 255) / 256, 256>>>(W2r, pwt + 3 * WSLOT, HH, CC);
    mask_comps_kernel<<<(CC * DD / 4 + 255) / 256, 256>>>(van, e_sp, pct);

    // energy MLP: h = relu(x@W1e+b1e); e = h@W2e+b2e
    tc_gemm<0><<<dim3(HH / 128, BB / 128), 256, DYN_SMEM>>>(
        px, pwt + 0 * WSLOT, b1e, nullptr, nullptr, ph, HH, DD);
    tc_gemm<1><<<dim3(CC / 128, BB / 128), 256, DYN_SMEM>>>(
        ph, pwt + 1 * WSLOT, b2e, nullptr, pe, nullptr, CC, HH);

    // Langevin gate (in place on g_e)
    gate_kernel<<<(BB * CC / 4 + 255) / 256, 256>>>(pe);

    // regressor MLP: hr = relu(x@W1r+b1r); conc = (hr@W2r+b2r)*gate
    tc_gemm<0><<<dim3(HH / 128, BB / 128), 256, DYN_SMEM>>>(
        px, pwt + 2 * WSLOT, b1r, nullptr, nullptr, ph, HH, DD);
    tc_gemm<2><<<dim3(CC / 128, BB / 128), 256, DYN_SMEM>>>(
        ph, pwt + 3 * WSLOT, b2r, pe, nullptr, pc, CC, HH);

    // aggregate: out = conc @ comps^T
    tc_gemm<3><<<dim3(DD / 128, BB / 128), 256, DYN_SMEM>>>(
        pc, pct, nullptr, nullptr, out, nullptr, DD, CC);
}